// round 10
// baseline (speedup 1.0000x reference)
#include <cuda_runtime.h>
#include <cstdint>

// LSTM encoder-decoder, GB300 sm_103a.
// N=2048 seqs, S=128 enc + 128 dec steps, H=128, F=13, gates G=512, K=F+H=141 (pad 144).
// grid=128 CTAs x 128 threads; CTA owns 16 sequences for all 256 steps (no inter-CTA sync).
// GEMM: 8seq x 8gate register tile per thread, packed fp32 FFMA2 (fma.rn.f32x2).
// Weights streamed from L2 via double-buffered cp.async (288KB fp32 doesn't fit SMEM).

#define NSEQ     16
#define THREADS  128
#define SEQS     2048
#define S_LEN    128
#define F_DIM    13
#define H_DIM    128
#define G_DIM    512
#define KV       141
#define KPAD     144
#define CH       16      // k-rows per staged chunk
#define NCH      9       // KPAD / CH
#define GB_STR   18      // gbuf row stride (pad vs 16 to kill bank conflicts)

__device__ float g_Wc[KPAD * G_DIM];   // combined [k][gate]: rows 0..12 = W_ih^T, 13..140 = W_hh^T, 141..143 = 0
__device__ float g_bc[G_DIM];          // b_ih + b_hh

typedef unsigned long long u64;

__device__ __forceinline__ u64 pack2(float a, float b){
    u64 r; asm("mov.b64 %0, {%1, %2};" : "=l"(r) : "f"(a), "f"(b)); return r;
}
__device__ __forceinline__ u64 ffma2(u64 a, u64 b, u64 c){
    u64 d; asm("fma.rn.f32x2 %0, %1, %2, %3;" : "=l"(d) : "l"(a), "l"(b), "l"(c)); return d;
}

// sigmoid / tanh via EX2 + approx-RCP (~1e-7 abs error; safe for 1e-3 rel over 256 steps)
__device__ __forceinline__ float fsig(float x){
    float e = __expf(-x);
    return __fdividef(1.0f, 1.0f + e);
}
__device__ __forceinline__ float ftanh_(float x){
    float e = __expf(-2.0f * x);
    return __fdividef(2.0f, 1.0f + e) - 1.0f;
}

__device__ __forceinline__ void cp_async16(uint32_t dst, const float* src){
    asm volatile("cp.async.cg.shared.global [%0], [%1], 16;\n" :: "r"(dst), "l"(src));
}
__device__ __forceinline__ void cp_commit(){
    asm volatile("cp.async.commit_group;\n" ::: "memory");
}
__device__ __forceinline__ void cp_wait_all(){
    asm volatile("cp.async.wait_group 0;\n" ::: "memory");
}

// ---------------- prep: build combined weight / bias ----------------
__global__ void prep_kernel(const float* __restrict__ Wih, const float* __restrict__ Whh,
                            const float* __restrict__ bih, const float* __restrict__ bhh){
    int i = blockIdx.x * blockDim.x + threadIdx.x;
    if (i < KPAD * G_DIM){
        int k = i / G_DIM, g = i % G_DIM;
        float v = 0.0f;
        if (k < F_DIM)      v = Wih[g * F_DIM + k];
        else if (k < KV)    v = Whh[g * H_DIM + (k - F_DIM)];
        g_Wc[i] = v;
    }
    if (i < G_DIM) g_bc[i] = bih[i] + bhh[i];
}

// ---------------- main persistent LSTM kernel ----------------
__global__ void __launch_bounds__(THREADS, 1) lstm_kernel(
    const float* __restrict__ X,     // [2048][128][13]
    const float* __restrict__ Wfc,   // [13][128]
    const float* __restrict__ bfc,   // [13]
    float* __restrict__ out)         // [2048*128 emb] ++ [2048*128*13 dec]
{
    extern __shared__ float smem[];
    float* s_w   = smem;                          // [2][CH][512]  = 16384 f
    float* s_inp = s_w   + 2 * CH * G_DIM;        // [144][16]     =  2304 f  (rows 0..12 x, 13..140 h, 141..143 zero)
    float* s_gb  = s_inp + KPAD * NSEQ;           // [512][18]     =  9216 f
    float* s_wfc = s_gb  + G_DIM * GB_STR;        // [13][128]     =  1664 f
    float* s_pb  = s_wfc + F_DIM * H_DIM;         // [13][128]     =  1664 f  (decoder partials)
    float* s_bfc = s_pb  + F_DIM * H_DIM;         // [16]

    const int tid = threadIdx.x;
    const int sb  = blockIdx.x * NSEQ;            // first sequence of this CTA
    const int sg  = tid >> 6;                     // seq group 0..1 (8 seqs each)
    const int gg  = tid & 63;                     // gate group 0..63 (gates gg + 64e)
    const int sA  = tid & 15;                     // activation: owned seq
    const int jb  = tid >> 4;                     // activation: j block 0..7
    const int j0  = jb * 16;

    // init shared
    for (int i = tid; i < KPAD * NSEQ; i += THREADS) s_inp[i] = 0.0f;
    for (int i = tid; i < F_DIM * H_DIM; i += THREADS) s_wfc[i] = Wfc[i];
    if (tid < F_DIM) s_bfc[tid] = bfc[tid];

    // bias pairs (const over all steps)
    u64 bpair[8];
    #pragma unroll
    for (int e = 0; e < 8; e++){
        float b = g_bc[gg + 64 * e];
        bpair[e] = pack2(b, b);
    }

    float creg[16];
    #pragma unroll
    for (int i = 0; i < 16; i++) creg[i] = 0.0f;

    // prefetch x_0 into registers (16 seqs x 13 feats = 208 values; tid covers 0..127, tid+128 covers 128..207)
    const int xs0 = tid / 13,        xf0 = tid % 13;
    const int xs1 = (tid + 128) / 13, xf1 = (tid + 128) % 13;
    float xr0, xr1 = 0.0f;
    xr0 = X[(size_t)(sb + xs0) * (S_LEN * F_DIM) + xf0];
    if (tid < 80) xr1 = X[(size_t)(sb + xs1) * (S_LEN * F_DIM) + xf1];

    __syncthreads();

    const uint32_t s_w_addr = (uint32_t)__cvta_generic_to_shared(s_w);
    const int COPIES = (CH * G_DIM) / (THREADS * 4);   // 16 x 16B per thread per chunk

    for (int t = 0; t < 2 * S_LEN; ++t){
        // ---- write x rows (encoder steps; decoder x written by previous step's projection) ----
        if (t < S_LEN){
            s_inp[xf0 * NSEQ + xs0] = xr0;
            if (tid < 80) s_inp[xf1 * NSEQ + xs1] = xr1;
        }
        __syncthreads();   // (A) inp fully formed for this step

        // prefetch next x during GEMM
        if (t + 1 < S_LEN){
            xr0 = X[(size_t)(sb + xs0) * (S_LEN * F_DIM) + (t + 1) * F_DIM + xf0];
            if (tid < 80) xr1 = X[(size_t)(sb + xs1) * (S_LEN * F_DIM) + (t + 1) * F_DIM + xf1];
        }

        // stage weight chunk 0
        {
            #pragma unroll
            for (int i = 0; i < COPIES; i++){
                int idx = (i * THREADS + tid) * 4;
                cp_async16(s_w_addr + idx * 4, g_Wc + idx);
            }
            cp_commit();
        }

        // accumulators = bias
        u64 acc[8][4];
        #pragma unroll
        for (int e = 0; e < 8; e++){
            #pragma unroll
            for (int p = 0; p < 4; p++) acc[e][p] = bpair[e];
        }

        // ---- GEMM over K=144 in 9 chunks of 16, double-buffered ----
        #pragma unroll 1
        for (int ch = 0; ch < NCH; ch++){
            cp_wait_all();
            __syncthreads();   // (B) chunk ch visible to all; all threads done with the buffer we refill next

            if (ch + 1 < NCH){
                const float* src = g_Wc + (ch + 1) * CH * G_DIM;
                uint32_t dbase = s_w_addr + (uint32_t)(((ch + 1) & 1) * CH * G_DIM * 4);
                #pragma unroll
                for (int i = 0; i < COPIES; i++){
                    int idx = (i * THREADS + tid) * 4;
                    cp_async16(dbase + idx * 4, src + idx);
                }
                cp_commit();
            }

            const float* wbuf = s_w + (ch & 1) * CH * G_DIM;
            const float* ibuf = s_inp + (ch * CH) * NSEQ + sg * 8;
            #pragma unroll
            for (int kk = 0; kk < CH; kk++){
                ulonglong2 ipa = *(const ulonglong2*)(ibuf + kk * NSEQ);       // seqs 0,1 | 2,3
                ulonglong2 ipb = *(const ulonglong2*)(ibuf + kk * NSEQ + 4);   // seqs 4,5 | 6,7
                const float* wr = wbuf + kk * G_DIM + gg;
                #pragma unroll
                for (int e = 0; e < 8; e++){
                    float w = wr[64 * e];
                    u64 wp = pack2(w, w);
                    acc[e][0] = ffma2(wp, ipa.x, acc[e][0]);
                    acc[e][1] = ffma2(wp, ipa.y, acc[e][1]);
                    acc[e][2] = ffma2(wp, ipb.x, acc[e][2]);
                    acc[e][3] = ffma2(wp, ipb.y, acc[e][3]);
                }
            }
        }

        // ---- store gates to SMEM ----
        {
            float* gb = s_gb + sg * 8;
            #pragma unroll
            for (int e = 0; e < 8; e++){
                int ge = gg + 64 * e;
                u64* row = (u64*)(gb + ge * GB_STR);
                row[0] = acc[e][0]; row[1] = acc[e][1];
                row[2] = acc[e][2]; row[3] = acc[e][3];
            }
        }
        __syncthreads();   // (C) gates visible; also: all GEMM reads of s_inp done

        // ---- activations: thread owns (seq sA, 16 h-units j0..j0+15), c state in registers ----
        float hreg[16];
        #pragma unroll
        for (int jj = 0; jj < 16; jj++){
            int j = j0 + jj;
            float gi = s_gb[(j      ) * GB_STR + sA];
            float gf = s_gb[(j + 128) * GB_STR + sA];
            float gc = s_gb[(j + 256) * GB_STR + sA];
            float go = s_gb[(j + 384) * GB_STR + sA];
            float c  = fsig(gf) * creg[jj] + fsig(gi) * ftanh_(gc);
            float h  = fsig(go) * ftanh_(c);
            creg[jj] = c;
            hreg[jj] = h;
            s_inp[(F_DIM + j) * NSEQ + sA] = h;    // h feeds next step's GEMM
        }

        // embeddings = h after last encoder step
        if (t == S_LEN - 1){
            float* emb = out + (size_t)(sb + sA) * H_DIM;
            #pragma unroll
            for (int jj = 0; jj < 16; jj++) emb[j0 + jj] = hreg[jj];
        }

        // ---- decoder: out = h @ Wfc^T + bfc; feeds next x ----
        if (t >= S_LEN){
            float po[13];
            #pragma unroll
            for (int f = 0; f < 13; f++) po[f] = 0.0f;
            #pragma unroll
            for (int jj = 0; jj < 16; jj++){
                float h = hreg[jj];
                const float* wf = s_wfc + (j0 + jj);
                #pragma unroll
                for (int f = 0; f < 13; f++) po[f] += h * wf[f * H_DIM];
            }
            #pragma unroll
            for (int f = 0; f < 13; f++) s_pb[f * H_DIM + jb * 16 + sA] = po[f];
            __syncthreads();   // (D) partials visible

            float* dec = out + (size_t)SEQS * H_DIM;
            int td = t - S_LEN;
            for (int idx = tid; idx < F_DIM * NSEQ; idx += THREADS){
                int f = idx >> 4, s2 = idx & 15;
                float sum = s_bfc[f];
                #pragma unroll
                for (int b = 0; b < 8; b++) sum += s_pb[f * H_DIM + b * 16 + s2];
                dec[(size_t)(sb + s2) * (S_LEN * F_DIM) + td * F_DIM + f] = sum;
                s_inp[f * NSEQ + s2] = sum;        // next decoder input
            }
        }
    }
}

// ---------------- launch ----------------
extern "C" void kernel_launch(void* const* d_in, const int* in_sizes, int n_in,
                              void* d_out, int out_size){
    const float* X    = (const float*)d_in[0];
    const float* Wih  = (const float*)d_in[1];
    const float* Whh  = (const float*)d_in[2];
    const float* bih  = (const float*)d_in[3];
    const float* bhh  = (const float*)d_in[4];
    const float* Wfc  = (const float*)d_in[5];
    const float* bfc  = (const float*)d_in[6];
    float* out = (float*)d_out;

    // combined weight/bias prep (tiny)
    prep_kernel<<<(KPAD * G_DIM + 255) / 256, 256>>>(Wih, Whh, bih, bhh);

    const int smem_floats = 2 * CH * G_DIM      // weight double buffer
                          + KPAD * NSEQ         // inp
                          + G_DIM * GB_STR      // gates
                          + F_DIM * H_DIM       // Wfc
                          + F_DIM * H_DIM       // partials
                          + 16;                 // bfc
    const int smem_bytes = smem_floats * (int)sizeof(float);   // ~125 KB

    cudaFuncSetAttribute(lstm_kernel, cudaFuncAttributeMaxDynamicSharedMemorySize, smem_bytes);

    lstm_kernel<<<SEQS / NSEQ, THREADS, smem_bytes>>>(X, Wfc, bfc, out);
}

// round 13
// speedup vs baseline: 1.0006x; 1.0006x over previous
#include <cuda_runtime.h>
#include <cstdint>

// LSTM encoder-decoder, GB300 sm_103a.
// N=2048 seqs, S=128 enc + 128 dec steps, H=128, F=13, gates G=512, K=F+H=141 (pad 144).
// grid=128 CTAs x 128 threads; CTA owns 16 sequences for all 256 steps (no inter-CTA sync).
// GEMM: 8seq x 8gate register tile per thread, packed fp32 FFMA2 (fma.rn.f32x2).
// Weights streamed from L2 via double-buffered cp.async (288KB fp32 doesn't fit SMEM).

#define NSEQ     16
#define THREADS  128
#define SEQS     2048
#define S_LEN    128
#define F_DIM    13
#define H_DIM    128
#define G_DIM    512
#define KV       141
#define KPAD     144
#define CH       16      // k-rows per staged chunk
#define NCH      9       // KPAD / CH
#define GB_STR   18      // gbuf row stride (pad vs 16 to kill bank conflicts)

__device__ float g_Wc[KPAD * G_DIM];   // combined [k][gate]: rows 0..12 = W_ih^T, 13..140 = W_hh^T, 141..143 = 0
__device__ float g_bc[G_DIM];          // b_ih + b_hh

typedef unsigned long long u64;

__device__ __forceinline__ u64 pack2(float a, float b){
    u64 r; asm("mov.b64 %0, {%1, %2};" : "=l"(r) : "f"(a), "f"(b)); return r;
}
__device__ __forceinline__ u64 ffma2(u64 a, u64 b, u64 c){
    u64 d; asm("fma.rn.f32x2 %0, %1, %2, %3;" : "=l"(d) : "l"(a), "l"(b), "l"(c)); return d;
}

// sigmoid / tanh via EX2 + approx-RCP (~1e-7 abs error; safe for 1e-3 rel over 256 steps)
__device__ __forceinline__ float fsig(float x){
    float e = __expf(-x);
    return __fdividef(1.0f, 1.0f + e);
}
__device__ __forceinline__ float ftanh_(float x){
    float e = __expf(-2.0f * x);
    return __fdividef(2.0f, 1.0f + e) - 1.0f;
}

__device__ __forceinline__ void cp_async16(uint32_t dst, const float* src){
    asm volatile("cp.async.cg.shared.global [%0], [%1], 16;\n" :: "r"(dst), "l"(src));
}
__device__ __forceinline__ void cp_commit(){
    asm volatile("cp.async.commit_group;\n" ::: "memory");
}
__device__ __forceinline__ void cp_wait_all(){
    asm volatile("cp.async.wait_group 0;\n" ::: "memory");
}

// ---------------- prep: build combined weight / bias ----------------
__global__ void prep_kernel(const float* __restrict__ Wih, const float* __restrict__ Whh,
                            const float* __restrict__ bih, const float* __restrict__ bhh){
    int i = blockIdx.x * blockDim.x + threadIdx.x;
    if (i < KPAD * G_DIM){
        int k = i / G_DIM, g = i % G_DIM;
        float v = 0.0f;
        if (k < F_DIM)      v = Wih[g * F_DIM + k];
        else if (k < KV)    v = Whh[g * H_DIM + (k - F_DIM)];
        g_Wc[i] = v;
    }
    if (i < G_DIM) g_bc[i] = bih[i] + bhh[i];
}

// ---------------- main persistent LSTM kernel ----------------
__global__ void __launch_bounds__(THREADS, 1) lstm_kernel(
    const float* __restrict__ X,     // [2048][128][13]
    const float* __restrict__ Wfc,   // [13][128]
    const float* __restrict__ bfc,   // [13]
    float* __restrict__ out)         // [2048*128 emb] ++ [2048*128*13 dec]
{
    extern __shared__ float smem[];
    float* s_w   = smem;                          // [2][CH][512]  = 16384 f
    float* s_inp = s_w   + 2 * CH * G_DIM;        // [144][16]     =  2304 f  (rows 0..12 x, 13..140 h, 141..143 zero)
    float* s_gb  = s_inp + KPAD * NSEQ;           // [512][18]     =  9216 f
    float* s_wfc = s_gb  + G_DIM * GB_STR;        // [13][128]     =  1664 f
    float* s_pb  = s_wfc + F_DIM * H_DIM;         // [13][128]     =  1664 f  (decoder partials)
    float* s_bfc = s_pb  + F_DIM * H_DIM;         // [16]

    const int tid = threadIdx.x;
    const int sb  = blockIdx.x * NSEQ;            // first sequence of this CTA
    const int sg  = tid >> 6;                     // seq group 0..1 (8 seqs each)
    const int gg  = tid & 63;                     // gate group 0..63 (gates gg + 64e)
    const int sA  = tid & 15;                     // activation: owned seq
    const int jb  = tid >> 4;                     // activation: j block 0..7
    const int j0  = jb * 16;

    // init shared
    for (int i = tid; i < KPAD * NSEQ; i += THREADS) s_inp[i] = 0.0f;
    for (int i = tid; i < F_DIM * H_DIM; i += THREADS) s_wfc[i] = Wfc[i];
    if (tid < F_DIM) s_bfc[tid] = bfc[tid];

    // bias pairs (const over all steps)
    u64 bpair[8];
    #pragma unroll
    for (int e = 0; e < 8; e++){
        float b = g_bc[gg + 64 * e];
        bpair[e] = pack2(b, b);
    }

    float creg[16];
    #pragma unroll
    for (int i = 0; i < 16; i++) creg[i] = 0.0f;

    // prefetch x_0 into registers (16 seqs x 13 feats = 208 values; tid covers 0..127, tid+128 covers 128..207)
    const int xs0 = tid / 13,        xf0 = tid % 13;
    const int xs1 = (tid + 128) / 13, xf1 = (tid + 128) % 13;
    float xr0, xr1 = 0.0f;
    xr0 = X[(size_t)(sb + xs0) * (S_LEN * F_DIM) + xf0];
    if (tid < 80) xr1 = X[(size_t)(sb + xs1) * (S_LEN * F_DIM) + xf1];

    __syncthreads();

    const uint32_t s_w_addr = (uint32_t)__cvta_generic_to_shared(s_w);
    const int COPIES = (CH * G_DIM) / (THREADS * 4);   // 16 x 16B per thread per chunk

    for (int t = 0; t < 2 * S_LEN; ++t){
        // ---- write x rows (encoder steps; decoder x written by previous step's projection) ----
        if (t < S_LEN){
            s_inp[xf0 * NSEQ + xs0] = xr0;
            if (tid < 80) s_inp[xf1 * NSEQ + xs1] = xr1;
        }
        __syncthreads();   // (A) inp fully formed for this step

        // prefetch next x during GEMM
        if (t + 1 < S_LEN){
            xr0 = X[(size_t)(sb + xs0) * (S_LEN * F_DIM) + (t + 1) * F_DIM + xf0];
            if (tid < 80) xr1 = X[(size_t)(sb + xs1) * (S_LEN * F_DIM) + (t + 1) * F_DIM + xf1];
        }

        // stage weight chunk 0
        {
            #pragma unroll
            for (int i = 0; i < COPIES; i++){
                int idx = (i * THREADS + tid) * 4;
                cp_async16(s_w_addr + idx * 4, g_Wc + idx);
            }
            cp_commit();
        }

        // accumulators = bias
        u64 acc[8][4];
        #pragma unroll
        for (int e = 0; e < 8; e++){
            #pragma unroll
            for (int p = 0; p < 4; p++) acc[e][p] = bpair[e];
        }

        // ---- GEMM over K=144 in 9 chunks of 16, double-buffered ----
        #pragma unroll 1
        for (int ch = 0; ch < NCH; ch++){
            cp_wait_all();
            __syncthreads();   // (B) chunk ch visible to all; all threads done with the buffer we refill next

            if (ch + 1 < NCH){
                const float* src = g_Wc + (ch + 1) * CH * G_DIM;
                uint32_t dbase = s_w_addr + (uint32_t)(((ch + 1) & 1) * CH * G_DIM * 4);
                #pragma unroll
                for (int i = 0; i < COPIES; i++){
                    int idx = (i * THREADS + tid) * 4;
                    cp_async16(dbase + idx * 4, src + idx);
                }
                cp_commit();
            }

            const float* wbuf = s_w + (ch & 1) * CH * G_DIM;
            const float* ibuf = s_inp + (ch * CH) * NSEQ + sg * 8;
            #pragma unroll
            for (int kk = 0; kk < CH; kk++){
                ulonglong2 ipa = *(const ulonglong2*)(ibuf + kk * NSEQ);       // seqs 0,1 | 2,3
                ulonglong2 ipb = *(const ulonglong2*)(ibuf + kk * NSEQ + 4);   // seqs 4,5 | 6,7
                const float* wr = wbuf + kk * G_DIM + gg;
                #pragma unroll
                for (int e = 0; e < 8; e++){
                    float w = wr[64 * e];
                    u64 wp = pack2(w, w);
                    acc[e][0] = ffma2(wp, ipa.x, acc[e][0]);
                    acc[e][1] = ffma2(wp, ipa.y, acc[e][1]);
                    acc[e][2] = ffma2(wp, ipb.x, acc[e][2]);
                    acc[e][3] = ffma2(wp, ipb.y, acc[e][3]);
                }
            }
        }

        // ---- store gates to SMEM ----
        {
            float* gb = s_gb + sg * 8;
            #pragma unroll
            for (int e = 0; e < 8; e++){
                int ge = gg + 64 * e;
                u64* row = (u64*)(gb + ge * GB_STR);
                row[0] = acc[e][0]; row[1] = acc[e][1];
                row[2] = acc[e][2]; row[3] = acc[e][3];
            }
        }
        __syncthreads();   // (C) gates visible; also: all GEMM reads of s_inp done

        // ---- activations: thread owns (seq sA, 16 h-units j0..j0+15), c state in registers ----
        float hreg[16];
        #pragma unroll
        for (int jj = 0; jj < 16; jj++){
            int j = j0 + jj;
            float gi = s_gb[(j      ) * GB_STR + sA];
            float gf = s_gb[(j + 128) * GB_STR + sA];
            float gc = s_gb[(j + 256) * GB_STR + sA];
            float go = s_gb[(j + 384) * GB_STR + sA];
            float c  = fsig(gf) * creg[jj] + fsig(gi) * ftanh_(gc);
            float h  = fsig(go) * ftanh_(c);
            creg[jj] = c;
            hreg[jj] = h;
            s_inp[(F_DIM + j) * NSEQ + sA] = h;    // h feeds next step's GEMM
        }

        // embeddings = h after last encoder step
        if (t == S_LEN - 1){
            float* emb = out + (size_t)(sb + sA) * H_DIM;
            #pragma unroll
            for (int jj = 0; jj < 16; jj++) emb[j0 + jj] = hreg[jj];
        }

        // ---- decoder: out = h @ Wfc^T + bfc; feeds next x ----
        if (t >= S_LEN){
            float po[13];
            #pragma unroll
            for (int f = 0; f < 13; f++) po[f] = 0.0f;
            #pragma unroll
            for (int jj = 0; jj < 16; jj++){
                float h = hreg[jj];
                const float* wf = s_wfc + (j0 + jj);
                #pragma unroll
                for (int f = 0; f < 13; f++) po[f] += h * wf[f * H_DIM];
            }
            #pragma unroll
            for (int f = 0; f < 13; f++) s_pb[f * H_DIM + jb * 16 + sA] = po[f];
            __syncthreads();   // (D) partials visible

            float* dec = out + (size_t)SEQS * H_DIM;
            int td = t - S_LEN;
            for (int idx = tid; idx < F_DIM * NSEQ; idx += THREADS){
                int f = idx >> 4, s2 = idx & 15;
                float sum = s_bfc[f];
                #pragma unroll
                for (int b = 0; b < 8; b++) sum += s_pb[f * H_DIM + b * 16 + s2];
                dec[(size_t)(sb + s2) * (S_LEN * F_DIM) + td * F_DIM + f] = sum;
                s_inp[f * NSEQ + s2] = sum;        // next decoder input
            }
        }
    }
}

// ---------------- launch ----------------
extern "C" void kernel_launch(void* const* d_in, const int* in_sizes, int n_in,
                              void* d_out, int out_size){
    const float* X    = (const float*)d_in[0];
    const float* Wih  = (const float*)d_in[1];
    const float* Whh  = (const float*)d_in[2];
    const float* bih  = (const float*)d_in[3];
    const float* bhh  = (const float*)d_in[4];
    const float* Wfc  = (const float*)d_in[5];
    const float* bfc  = (const float*)d_in[6];
    float* out = (float*)d_out;

    // combined weight/bias prep (tiny)
    prep_kernel<<<(KPAD * G_DIM + 255) / 256, 256>>>(Wih, Whh, bih, bhh);

    const int smem_floats = 2 * CH * G_DIM      // weight double buffer
                          + KPAD * NSEQ         // inp
                          + G_DIM * GB_STR      // gates
                          + F_DIM * H_DIM       // Wfc
                          + F_DIM * H_DIM       // partials
                          + 16;                 // bfc
    const int smem_bytes = smem_floats * (int)sizeof(float);   // ~125 KB

    cudaFuncSetAttribute(lstm_kernel, cudaFuncAttributeMaxDynamicSharedMemorySize, smem_bytes);

    lstm_kernel<<<SEQS / NSEQ, THREADS, smem_bytes>>>(X, Wfc, bfc, out);
}